// round 9
// baseline (speedup 1.0000x reference)
#include <cuda_runtime.h>
#include <cuda_fp16.h>
#include <cstdint>
#include <math.h>

// ---------------------------------------------------------------------------
// PFMLPScaledXY via fp16 mma.sync.m16n8k16 (ptxas target = plain sm_100).
//   Lk(inp) = p0*(inp@Wk0) + p1*(inp@Wk1) + p0*bk0 + p1*bk1
// R9 vs R8 (494us, tensor=75%): the K-loop __syncthreads rendezvous is the
// structural bubble (R6/R8 instruction reordering neutral, R7 1-CTA/SM worse).
// Replace with mbarrier producer/consumer pipeline:
//   full[s] (count 256): cp.async.mbarrier.arrive.noinc per thread
//   empty[s] (count 8):  one arrive per warp at stage-consume end
// Warps proceed independently; fast warps start the next stage's ldsm/MMA
// while slow warps finish -> decorrelated, tensor pipe stays fed.
// ---------------------------------------------------------------------------

#define NTHREADS 256
#define TBM 128
#define TBN 64      // per mode
#define TBK 64

// scratch (__device__ globals: allocation-free rule)
__device__ __half g_xh [32768ull * 256];
__device__ __half g_w1h[2ull * 256 * 1024];
__device__ __half g_w2h[2ull * 1024 * 1024];
__device__ __half g_w3h[2ull * 1024 * 64];
__device__ __half g_h1 [32768ull * 1024];
__device__ __half g_h2 [32768ull * 1024];

// ---------------- PTX helpers ----------------------------------------------
__device__ __forceinline__ uint32_t smem_u32(const void* p) {
    return (uint32_t)__cvta_generic_to_shared(p);
}
__device__ __forceinline__ void cp_async16(uint32_t s, const void* g) {
    asm volatile("cp.async.cg.shared.global [%0], [%1], 16;" :: "r"(s), "l"(g));
}
__device__ __forceinline__ void ldsm_x4(uint32_t* r, uint32_t a) {
    asm volatile("ldmatrix.sync.aligned.m8n8.x4.shared.b16 {%0,%1,%2,%3}, [%4];"
                 : "=r"(r[0]), "=r"(r[1]), "=r"(r[2]), "=r"(r[3]) : "r"(a));
}
__device__ __forceinline__ void ldsm_x4_t(uint32_t* r, uint32_t a) {
    asm volatile("ldmatrix.sync.aligned.m8n8.x4.trans.shared.b16 {%0,%1,%2,%3}, [%4];"
                 : "=r"(r[0]), "=r"(r[1]), "=r"(r[2]), "=r"(r[3]) : "r"(a));
}
__device__ __forceinline__ void mma_f16(float* d, const uint32_t* a,
                                        uint32_t b0, uint32_t b1) {
    asm volatile(
        "mma.sync.aligned.m16n8k16.row.col.f32.f16.f16.f32 "
        "{%0,%1,%2,%3}, {%4,%5,%6,%7}, {%8,%9}, {%0,%1,%2,%3};"
        : "+f"(d[0]), "+f"(d[1]), "+f"(d[2]), "+f"(d[3])
        : "r"(a[0]), "r"(a[1]), "r"(a[2]), "r"(a[3]), "r"(b0), "r"(b1));
}
// ---- mbarrier ----
__device__ __forceinline__ void mbar_init(uint32_t a, uint32_t c) {
    asm volatile("mbarrier.init.shared.b64 [%0], %1;" :: "r"(a), "r"(c) : "memory");
}
__device__ __forceinline__ void mbar_arrive(uint32_t a) {
    asm volatile("mbarrier.arrive.shared.b64 _, [%0];" :: "r"(a) : "memory");
}
__device__ __forceinline__ void cp_mbar_arrive_noinc(uint32_t a) {
    asm volatile("cp.async.mbarrier.arrive.noinc.shared.b64 [%0];" :: "r"(a) : "memory");
}
__device__ __forceinline__ void mbar_wait(uint32_t a, uint32_t ph) {
    asm volatile(
        "{\n\t.reg .pred P;\n\t"
        "WL%=:\n\t"
        "mbarrier.try_wait.parity.acquire.cta.shared::cta.b64 P, [%0], %1, 0x989680;\n\t"
        "@P bra WD%=;\n\t"
        "bra WL%=;\n\t"
        "WD%=:\n\t}"
        :: "r"(a), "r"(ph) : "memory");
}

// ---------------- preprocessing --------------------------------------------
// x [M,258] f32 -> xh [M,256] half (float2 only: row stride 1032B = 8 mod 16)
__global__ void conv_x_kernel(const float* __restrict__ x, __half* __restrict__ xh) {
    size_t idx = (size_t)blockIdx.x * blockDim.x + threadIdx.x;
    size_t r = idx >> 7;
    int c = (int)(idx & 127) * 2;
    float2 v = *reinterpret_cast<const float2*>(x + r * 258 + c);
    *reinterpret_cast<__half2*>(xh + r * 256 + c) = __floats2half2_rn(v.x, v.y);
}
__global__ void conv_w3_kernel(const float* __restrict__ w1, __half* __restrict__ w1h,
                               const float* __restrict__ w2, __half* __restrict__ w2h,
                               const float* __restrict__ w3, __half* __restrict__ w3h,
                               int n1, int n2, int n3) {
    int idx = blockIdx.x * blockDim.x + threadIdx.x;
    const float* src; __half* dst; int i;
    if (idx < n1)                { src = w1; dst = w1h; i = idx; }
    else if (idx < n1 + n2)      { src = w2; dst = w2h; i = idx - n1; }
    else if (idx < n1 + n2 + n3) { src = w3; dst = w3h; i = idx - n1 - n2; }
    else return;
    float4 v = reinterpret_cast<const float4*>(src)[i];
    reinterpret_cast<__half2*>(dst)[i * 2]     = __floats2half2_rn(v.x, v.y);
    reinterpret_cast<__half2*>(dst)[i * 2 + 1] = __floats2half2_rn(v.z, v.w);
}

// ---------------- main GEMM ------------------------------------------------
// A [Mtot,K] half row-major (lda == K), B [2][K,ldb] half row-major.
// Per CTA: rows blockM..+128, cols blockN..+64 (both modes).
// SMEM tile: 128-byte rows (64 halves); 16B chunk j of row m stored at chunk
// (j ^ (m&7)) -> conflict-free for cp.async writes AND ldmatrix reads.
template <int K, bool DO_ELU, bool OUT_HALF>
__global__ void __launch_bounds__(NTHREADS, 2) hgemm(
    const __half* __restrict__ A,
    const __half* __restrict__ B, size_t modeStride, int ldb,
    const float* __restrict__ bias0, const float* __restrict__ bias1,
    const float* __restrict__ xphase,
    void* __restrict__ Cv, int ldc)
{
    constexpr int A_BYTES = TBM * 128;              // 16384
    constexpr int B_BYTES = TBK * 128;              // 8192 per mode
    constexpr int STAGE   = A_BYTES + 2 * B_BYTES;  // 32768
    constexpr int NK      = K / TBK;

    extern __shared__ char smem[];
    const uint32_t sm = smem_u32(smem);
    const uint32_t mb_full  = sm + 3 * STAGE;        // 3 x 8B
    const uint32_t mb_empty = mb_full + 24;          // 3 x 8B

    const int tid  = threadIdx.x;
    const int wid  = tid >> 5;
    const int lane = tid & 31;
    const int warp_m = wid & 3;      // 4 warps over M (32 rows)
    const int warp_n = wid >> 2;     // 2 warps over N (32 cols)
    const size_t blockM = (size_t)blockIdx.y * TBM;
    const int blockN = blockIdx.x * TBN;

    if (tid == 0) {
        #pragma unroll
        for (int s = 0; s < 3; s++) {
            mbar_init(mb_full + s * 8, NTHREADS);
            mbar_init(mb_empty + s * 8, 8);
        }
    }
    __syncthreads();

    float acc[2][2][4][4];           // [mode][mtile][ntile][frag]
    #pragma unroll
    for (int m = 0; m < 2; m++)
        #pragma unroll
        for (int i = 0; i < 2; i++)
            #pragma unroll
            for (int j = 0; j < 4; j++)
                #pragma unroll
                for (int q = 0; q < 4; q++) acc[m][i][j][q] = 0.0f;

    auto load_stage = [&](int kt, int buf) {
        const int k0 = kt * TBK;
        const uint32_t st = sm + buf * STAGE;
        #pragma unroll
        for (int c = 0; c < 4; c++) {
            int p = c * NTHREADS + tid;
            int row = p >> 3, j = p & 7;
            uint32_t dst = st + row * 128 + ((j ^ (row & 7)) << 4);
            cp_async16(dst, A + (blockM + row) * (size_t)K + k0 + j * 8);
        }
        #pragma unroll
        for (int m = 0; m < 2; m++) {
            const __half* Bm = B + m * modeStride;
            const uint32_t bst = st + A_BYTES + m * B_BYTES;
            #pragma unroll
            for (int c = 0; c < 2; c++) {
                int p = c * NTHREADS + tid;
                int row = p >> 3, j = p & 7;
                uint32_t dst = bst + row * 128 + ((j ^ (row & 7)) << 4);
                cp_async16(dst, Bm + (size_t)(k0 + row) * ldb + blockN + j * 8);
            }
        }
        cp_mbar_arrive_noinc(mb_full + buf * 8);
    };

    // prologue: stages 0,1 (stage 2 issued in iter 0)
    load_stage(0, 0);
    load_stage(1, 1);

    #pragma unroll
    for (int i = 0; i < NK; i++) {
        const int kt = i + 2;
        if (kt < NK) {
            const int s = kt % 3;
            if (kt >= 3) mbar_wait(mb_empty + s * 8, (kt / 3 - 1) & 1);
            load_stage(kt, s);
        }

        const int cs = i % 3;
        mbar_wait(mb_full + cs * 8, (i / 3) & 1);
        const uint32_t st = sm + cs * STAGE;

        #pragma unroll
        for (int kk = 0; kk < 4; kk++) {
            uint32_t a[2][4];
            const int jA = kk * 2 + (lane >> 4);
            #pragma unroll
            for (int mt = 0; mt < 2; mt++) {
                const int m = warp_m * 32 + mt * 16 + (lane & 15);
                ldsm_x4(a[mt], st + m * 128 + ((jA ^ (m & 7)) << 4));
            }
            const int krow = kk * 16 + (lane & 15);
            #pragma unroll
            for (int m = 0; m < 2; m++) {
                const uint32_t bst = st + A_BYTES + m * B_BYTES;
                #pragma unroll
                for (int ntg = 0; ntg < 2; ntg++) {
                    const int jn = warp_n * 4 + ntg * 2 + (lane >> 4);
                    uint32_t b[4];
                    ldsm_x4_t(b, bst + krow * 128 + ((jn ^ (krow & 7)) << 4));
                    mma_f16(acc[m][0][ntg * 2 + 0], a[0], b[0], b[1]);
                    mma_f16(acc[m][0][ntg * 2 + 1], a[0], b[2], b[3]);
                    mma_f16(acc[m][1][ntg * 2 + 0], a[1], b[0], b[1]);
                    mma_f16(acc[m][1][ntg * 2 + 1], a[1], b[2], b[3]);
                }
            }
        }
        // warp done reading stage cs (ldmatrix is warp-collective, retired)
        if (lane == 0) mbar_arrive(mb_empty + cs * 8);
    }

    // ---- epilogue: phase mix + bias + ELU ----------------------------------
    #pragma unroll
    for (int mt = 0; mt < 2; mt++) {
        #pragma unroll
        for (int rr = 0; rr < 2; rr++) {
            const size_t r = blockM + warp_m * 32 + mt * 16 + rr * 8 + (lane >> 2);
            const float2 ph = *reinterpret_cast<const float2*>(xphase + r * 258 + 256);
            const float p0 = ph.x, p1 = ph.y;
            #pragma unroll
            for (int nt = 0; nt < 4; nt++) {
                const int col = blockN + warp_n * 32 + nt * 8 + (lane & 3) * 2;
                float v0 = p0 * acc[0][mt][nt][rr * 2 + 0]
                         + p1 * acc[1][mt][nt][rr * 2 + 0]
                         + p0 * __ldg(bias0 + col) + p1 * __ldg(bias1 + col);
                float v1 = p0 * acc[0][mt][nt][rr * 2 + 1]
                         + p1 * acc[1][mt][nt][rr * 2 + 1]
                         + p0 * __ldg(bias0 + col + 1) + p1 * __ldg(bias1 + col + 1);
                if (DO_ELU) {
                    v0 = v0 > 0.0f ? v0 : expm1f(v0);
                    v1 = v1 > 0.0f ? v1 : expm1f(v1);
                }
                if (OUT_HALF) {
                    __half* C = (__half*)Cv;
                    *reinterpret_cast<__half2*>(C + r * ldc + col) =
                        __floats2half2_rn(v0, v1);
                } else {
                    float* C = (float*)Cv;
                    *reinterpret_cast<float2*>(C + r * ldc + col) =
                        make_float2(v0, v1);
                }
            }
        }
    }
}

// ---------------------------------------------------------------------------
extern "C" void kernel_launch(void* const* d_in, const int* in_sizes, int n_in,
                              void* d_out, int out_size)
{
    const float* x  = (const float*)d_in[0];
    const float* w1 = (const float*)d_in[1];
    const float* b1 = (const float*)d_in[2];
    const float* w2 = (const float*)d_in[3];
    const float* b2 = (const float*)d_in[4];
    const float* w3 = (const float*)d_in[5];
    const float* b3 = (const float*)d_in[6];
    float* out = (float*)d_out;

    const int M = 32768, DIN = 256, H = 1024, DOUT = 64;

    __half *xh, *w1h, *w2h, *w3h, *h1, *h2;
    cudaGetSymbolAddress((void**)&xh,  g_xh);
    cudaGetSymbolAddress((void**)&w1h, g_w1h);
    cudaGetSymbolAddress((void**)&w2h, g_w2h);
    cudaGetSymbolAddress((void**)&w3h, g_w3h);
    cudaGetSymbolAddress((void**)&h1,  g_h1);
    cudaGetSymbolAddress((void**)&h2,  g_h2);

    const int SMEM = 3 * (128 * 128 + 2 * 64 * 128) + 64;   // stages + mbarriers
    cudaFuncSetAttribute((const void*)hgemm<256, true, true>,
                         cudaFuncAttributeMaxDynamicSharedMemorySize, SMEM);
    cudaFuncSetAttribute((const void*)hgemm<1024, true, true>,
                         cudaFuncAttributeMaxDynamicSharedMemorySize, SMEM);
    cudaFuncSetAttribute((const void*)hgemm<1024, false, false>,
                         cudaFuncAttributeMaxDynamicSharedMemorySize, SMEM);

    conv_x_kernel<<<M * 128 / 256, 256>>>(x, xh);
    {
        int n1 = 2 * DIN * H / 4, n2 = 2 * H * H / 4, n3 = 2 * H * DOUT / 4;
        conv_w3_kernel<<<(n1 + n2 + n3 + 255) / 256, 256>>>(
            w1, w1h, w2, w2h, w3, w3h, n1, n2, n3);
    }

    dim3 blk(NTHREADS);
    // L1: xh @ w1 -> elu -> h1 (half)
    hgemm<256, true, true><<<dim3(H / TBN, M / TBM), blk, SMEM>>>(
        xh, w1h, (size_t)DIN * H, H, b1, b1 + H, x, h1, H);
    // L2: h1 @ w2 -> elu -> h2 (half)
    hgemm<1024, true, true><<<dim3(H / TBN, M / TBM), blk, SMEM>>>(
        h1, w2h, (size_t)H * H, H, b2, b2 + H, x, h2, H);
    // L3: h2 @ w3 -> out (f32)
    hgemm<1024, false, false><<<dim3(DOUT / TBN, M / TBM), blk, SMEM>>>(
        h2, w3h, (size_t)H * DOUT, DOUT, b3, b3 + DOUT, x, out, DOUT);
}

// round 10
// speedup vs baseline: 1.1562x; 1.1562x over previous
#include <cuda_runtime.h>
#include <cuda_fp16.h>
#include <cstdint>
#include <math.h>

// ---------------------------------------------------------------------------
// PFMLPScaledXY via fp16 mma.sync.m16n8k16 (ptxas target = plain sm_100).
//   Lk(inp) = p0*(inp@Wk0) + p1*(inp@Wk1) + p0*bk0 + p1*bk1
// R10: revert to the R4 mainloop (best measured 491.5us, tensor=76%) after
// R6/R8 (reorderings: neutral), R7 (big tiles: -20%), R9 (mbarrier: -9%)
// established it as the local optimum under the RF/smem/occupancy lattice.
// Micro-wins only: fast ELU (__expf-1 instead of expm1f) and a peeled final
// K-iteration (branchless mainloop).
// ---------------------------------------------------------------------------

#define NTHREADS 256
#define TBM 128
#define TBN 64      // per mode
#define TBK 64

// scratch (__device__ globals: allocation-free rule)
__device__ __half g_xh [32768ull * 256];
__device__ __half g_w1h[2ull * 256 * 1024];
__device__ __half g_w2h[2ull * 1024 * 1024];
__device__ __half g_w3h[2ull * 1024 * 64];
__device__ __half g_h1 [32768ull * 1024];
__device__ __half g_h2 [32768ull * 1024];

// ---------------- PTX helpers ----------------------------------------------
__device__ __forceinline__ uint32_t smem_u32(const void* p) {
    return (uint32_t)__cvta_generic_to_shared(p);
}
__device__ __forceinline__ void cp_async16(uint32_t s, const void* g) {
    asm volatile("cp.async.cg.shared.global [%0], [%1], 16;" :: "r"(s), "l"(g));
}
__device__ __forceinline__ void cp_commit() {
    asm volatile("cp.async.commit_group;");
}
template <int N> __device__ __forceinline__ void cp_wait() {
    asm volatile("cp.async.wait_group %0;" :: "n"(N));
}
__device__ __forceinline__ void ldsm_x4(uint32_t* r, uint32_t a) {
    asm volatile("ldmatrix.sync.aligned.m8n8.x4.shared.b16 {%0,%1,%2,%3}, [%4];"
                 : "=r"(r[0]), "=r"(r[1]), "=r"(r[2]), "=r"(r[3]) : "r"(a));
}
__device__ __forceinline__ void ldsm_x4_t(uint32_t* r, uint32_t a) {
    asm volatile("ldmatrix.sync.aligned.m8n8.x4.trans.shared.b16 {%0,%1,%2,%3}, [%4];"
                 : "=r"(r[0]), "=r"(r[1]), "=r"(r[2]), "=r"(r[3]) : "r"(a));
}
__device__ __forceinline__ void mma_f16(float* d, const uint32_t* a,
                                        uint32_t b0, uint32_t b1) {
    asm volatile(
        "mma.sync.aligned.m16n8k16.row.col.f32.f16.f16.f32 "
        "{%0,%1,%2,%3}, {%4,%5,%6,%7}, {%8,%9}, {%0,%1,%2,%3};"
        : "+f"(d[0]), "+f"(d[1]), "+f"(d[2]), "+f"(d[3])
        : "r"(a[0]), "r"(a[1]), "r"(a[2]), "r"(a[3]), "r"(b0), "r"(b1));
}
__device__ __forceinline__ float elu_fast(float v) {
    // __expf (MUFU-based) vs expm1f: ~1e-7 abs error, far under tolerance
    return v > 0.0f ? v : (__expf(v) - 1.0f);
}

// ---------------- preprocessing --------------------------------------------
// x [M,258] f32 -> xh [M,256] half (float2 only: row stride 1032B = 8 mod 16)
__global__ void conv_x_kernel(const float* __restrict__ x, __half* __restrict__ xh) {
    size_t idx = (size_t)blockIdx.x * blockDim.x + threadIdx.x;
    size_t r = idx >> 7;
    int c = (int)(idx & 127) * 2;
    float2 v = *reinterpret_cast<const float2*>(x + r * 258 + c);
    *reinterpret_cast<__half2*>(xh + r * 256 + c) = __floats2half2_rn(v.x, v.y);
}
__global__ void conv_w3_kernel(const float* __restrict__ w1, __half* __restrict__ w1h,
                               const float* __restrict__ w2, __half* __restrict__ w2h,
                               const float* __restrict__ w3, __half* __restrict__ w3h,
                               int n1, int n2, int n3) {
    int idx = blockIdx.x * blockDim.x + threadIdx.x;
    const float* src; __half* dst; int i;
    if (idx < n1)                { src = w1; dst = w1h; i = idx; }
    else if (idx < n1 + n2)      { src = w2; dst = w2h; i = idx - n1; }
    else if (idx < n1 + n2 + n3) { src = w3; dst = w3h; i = idx - n1 - n2; }
    else return;
    float4 v = reinterpret_cast<const float4*>(src)[i];
    reinterpret_cast<__half2*>(dst)[i * 2]     = __floats2half2_rn(v.x, v.y);
    reinterpret_cast<__half2*>(dst)[i * 2 + 1] = __floats2half2_rn(v.z, v.w);
}

// ---------------- main GEMM ------------------------------------------------
// A [Mtot,K] half row-major (lda == K), B [2][K,ldb] half row-major.
// Per CTA: rows blockM..+128, cols blockN..+64 (both modes).
// SMEM tile: 128-byte rows (64 halves); 16B chunk j of row m stored at chunk
// (j ^ (m&7)) -> conflict-free for cp.async writes AND ldmatrix reads.
template <int K, bool DO_ELU, bool OUT_HALF>
__global__ void __launch_bounds__(NTHREADS, 2) hgemm(
    const __half* __restrict__ A,
    const __half* __restrict__ B, size_t modeStride, int ldb,
    const float* __restrict__ bias0, const float* __restrict__ bias1,
    const float* __restrict__ xphase,
    void* __restrict__ Cv, int ldc)
{
    constexpr int A_BYTES = TBM * 128;              // 16384
    constexpr int B_BYTES = TBK * 128;              // 8192 per mode
    constexpr int STAGE   = A_BYTES + 2 * B_BYTES;  // 32768
    constexpr int NK      = K / TBK;

    extern __shared__ char smem[];
    const uint32_t sm = smem_u32(smem);

    const int tid  = threadIdx.x;
    const int wid  = tid >> 5;
    const int lane = tid & 31;
    const int warp_m = wid & 3;      // 4 warps over M (32 rows)
    const int warp_n = wid >> 2;     // 2 warps over N (32 cols)
    const size_t blockM = (size_t)blockIdx.y * TBM;
    const int blockN = blockIdx.x * TBN;

    float acc[2][2][4][4];           // [mode][mtile][ntile][frag]
    #pragma unroll
    for (int m = 0; m < 2; m++)
        #pragma unroll
        for (int i = 0; i < 2; i++)
            #pragma unroll
            for (int j = 0; j < 4; j++)
                #pragma unroll
                for (int q = 0; q < 4; q++) acc[m][i][j][q] = 0.0f;

    auto load_stage = [&](int kt, int buf) {
        const int k0 = kt * TBK;
        const uint32_t st = sm + buf * STAGE;
        // A: 128 rows x 8 chunks = 1024 chunks, 4/thread
        #pragma unroll
        for (int c = 0; c < 4; c++) {
            int p = c * NTHREADS + tid;
            int row = p >> 3, j = p & 7;
            uint32_t dst = st + row * 128 + ((j ^ (row & 7)) << 4);
            cp_async16(dst, A + (blockM + row) * (size_t)K + k0 + j * 8);
        }
        // B: per mode 64 rows x 8 chunks = 512 chunks, 2/thread
        #pragma unroll
        for (int m = 0; m < 2; m++) {
            const __half* Bm = B + m * modeStride;
            const uint32_t bst = st + A_BYTES + m * B_BYTES;
            #pragma unroll
            for (int c = 0; c < 2; c++) {
                int p = c * NTHREADS + tid;
                int row = p >> 3, j = p & 7;
                uint32_t dst = bst + row * 128 + ((j ^ (row & 7)) << 4);
                cp_async16(dst, Bm + (size_t)(k0 + row) * ldb + blockN + j * 8);
            }
        }
        cp_commit();
    };

    auto consume_stage = [&](int i) {
        const uint32_t st = sm + (i % 3) * STAGE;
        #pragma unroll
        for (int kk = 0; kk < 4; kk++) {
            uint32_t a[2][4];
            const int jA = kk * 2 + (lane >> 4);
            #pragma unroll
            for (int mt = 0; mt < 2; mt++) {
                const int m = warp_m * 32 + mt * 16 + (lane & 15);
                ldsm_x4(a[mt], st + m * 128 + ((jA ^ (m & 7)) << 4));
            }
            const int krow = kk * 16 + (lane & 15);
            #pragma unroll
            for (int m = 0; m < 2; m++) {
                const uint32_t bst = st + A_BYTES + m * B_BYTES;
                #pragma unroll
                for (int ntg = 0; ntg < 2; ntg++) {
                    const int jn = warp_n * 4 + ntg * 2 + (lane >> 4);
                    uint32_t b[4];
                    ldsm_x4_t(b, bst + krow * 128 + ((jn ^ (krow & 7)) << 4));
                    mma_f16(acc[m][0][ntg * 2 + 0], a[0], b[0], b[1]);
                    mma_f16(acc[m][0][ntg * 2 + 1], a[0], b[2], b[3]);
                    mma_f16(acc[m][1][ntg * 2 + 0], a[1], b[0], b[1]);
                    mma_f16(acc[m][1][ntg * 2 + 1], a[1], b[2], b[3]);
                }
            }
        }
    };

    // 3-stage circular pipeline, loads 2 ahead, ONE barrier per iteration.
    load_stage(0, 0);
    load_stage(1, 1);

    #pragma unroll
    for (int i = 0; i < NK - 1; i++) {
        cp_wait<1>();
        __syncthreads();                       // all warps done with buf (i-1)%3
        if (i + 2 < NK) load_stage(i + 2, (i + 2) % 3);
        consume_stage(i);
    }
    // peeled final iteration (no further loads, drain all)
    cp_wait<0>();
    __syncthreads();
    consume_stage(NK - 1);

    // ---- epilogue: phase mix + bias + ELU ----------------------------------
    #pragma unroll
    for (int mt = 0; mt < 2; mt++) {
        #pragma unroll
        for (int rr = 0; rr < 2; rr++) {
            const size_t r = blockM + warp_m * 32 + mt * 16 + rr * 8 + (lane >> 2);
            const float2 ph = *reinterpret_cast<const float2*>(xphase + r * 258 + 256);
            const float p0 = ph.x, p1 = ph.y;
            #pragma unroll
            for (int nt = 0; nt < 4; nt++) {
                const int col = blockN + warp_n * 32 + nt * 8 + (lane & 3) * 2;
                float v0 = p0 * acc[0][mt][nt][rr * 2 + 0]
                         + p1 * acc[1][mt][nt][rr * 2 + 0]
                         + p0 * __ldg(bias0 + col) + p1 * __ldg(bias1 + col);
                float v1 = p0 * acc[0][mt][nt][rr * 2 + 1]
                         + p1 * acc[1][mt][nt][rr * 2 + 1]
                         + p0 * __ldg(bias0 + col + 1) + p1 * __ldg(bias1 + col + 1);
                if (DO_ELU) {
                    v0 = elu_fast(v0);
                    v1 = elu_fast(v1);
                }
                if (OUT_HALF) {
                    __half* C = (__half*)Cv;
                    *reinterpret_cast<__half2*>(C + r * ldc + col) =
                        __floats2half2_rn(v0, v1);
                } else {
                    float* C = (float*)Cv;
                    *reinterpret_cast<float2*>(C + r * ldc + col) =
                        make_float2(v0, v1);
                }
            }
        }
    }
}

// ---------------------------------------------------------------------------
extern "C" void kernel_launch(void* const* d_in, const int* in_sizes, int n_in,
                              void* d_out, int out_size)
{
    const float* x  = (const float*)d_in[0];
    const float* w1 = (const float*)d_in[1];
    const float* b1 = (const float*)d_in[2];
    const float* w2 = (const float*)d_in[3];
    const float* b2 = (const float*)d_in[4];
    const float* w3 = (const float*)d_in[5];
    const float* b3 = (const float*)d_in[6];
    float* out = (float*)d_out;

    const int M = 32768, DIN = 256, H = 1024, DOUT = 64;

    __half *xh, *w1h, *w2h, *w3h, *h1, *h2;
    cudaGetSymbolAddress((void**)&xh,  g_xh);
    cudaGetSymbolAddress((void**)&w1h, g_w1h);
    cudaGetSymbolAddress((void**)&w2h, g_w2h);
    cudaGetSymbolAddress((void**)&w3h, g_w3h);
    cudaGetSymbolAddress((void**)&h1,  g_h1);
    cudaGetSymbolAddress((void**)&h2,  g_h2);

    const int SMEM = 3 * (128 * 128 + 2 * 64 * 128);   // 98304 (3 stages)
    cudaFuncSetAttribute((const void*)hgemm<256, true, true>,
                         cudaFuncAttributeMaxDynamicSharedMemorySize, SMEM);
    cudaFuncSetAttribute((const void*)hgemm<1024, true, true>,
                         cudaFuncAttributeMaxDynamicSharedMemorySize, SMEM);
    cudaFuncSetAttribute((const void*)hgemm<1024, false, false>,
                         cudaFuncAttributeMaxDynamicSharedMemorySize, SMEM);

    conv_x_kernel<<<M * 128 / 256, 256>>>(x, xh);
    {
        int n1 = 2 * DIN * H / 4, n2 = 2 * H * H / 4, n3 = 2 * H * DOUT / 4;
        conv_w3_kernel<<<(n1 + n2 + n3 + 255) / 256, 256>>>(
            w1, w1h, w2, w2h, w3, w3h, n1, n2, n3);
    }

    dim3 blk(NTHREADS);
    // L1: xh @ w1 -> elu -> h1 (half)
    hgemm<256, true, true><<<dim3(H / TBN, M / TBM), blk, SMEM>>>(
        xh, w1h, (size_t)DIN * H, H, b1, b1 + H, x, h1, H);
    // L2: h1 @ w2 -> elu -> h2 (half)
    hgemm<1024, true, true><<<dim3(H / TBN, M / TBM), blk, SMEM>>>(
        h1, w2h, (size_t)H * H, H, b2, b2 + H, x, h2, H);
    // L3: h2 @ w3 -> out (f32)
    hgemm<1024, false, false><<<dim3(DOUT / TBN, M / TBM), blk, SMEM>>>(
        h2, w3h, (size_t)H * DOUT, DOUT, b3, b3 + DOUT, x, out, DOUT);
}

// round 12
// speedup vs baseline: 1.1794x; 1.0200x over previous
#include <cuda_runtime.h>
#include <cuda_fp16.h>
#include <cstdint>
#include <math.h>

// ---------------------------------------------------------------------------
// PFMLPScaledXY via fp16 mma.sync.m16n8k16 (ptxas target = plain sm_100).
//   Lk(inp) = p0*(inp@Wk0) + p1*(inp@Wk1) + p0*bk0 + p1*bk1
// R12 = R11 retry (fused preprocessing, 16B x stores) with the nonexistent
// __half2_as_uint replaced by a __half2_raw bit-cast. GEMM mainloop is the
// converged R10 version (465.9us, tensor=77.9%).
// ---------------------------------------------------------------------------

#define NTHREADS 256
#define TBM 128
#define TBN 64      // per mode
#define TBK 64

// scratch (__device__ globals: allocation-free rule)
__device__ __half g_xh [32768ull * 256];
__device__ __half g_w1h[2ull * 256 * 1024];
__device__ __half g_w2h[2ull * 1024 * 1024];
__device__ __half g_w3h[2ull * 1024 * 64];
__device__ __half g_h1 [32768ull * 1024];
__device__ __half g_h2 [32768ull * 1024];

// ---------------- PTX helpers ----------------------------------------------
__device__ __forceinline__ uint32_t smem_u32(const void* p) {
    return (uint32_t)__cvta_generic_to_shared(p);
}
__device__ __forceinline__ void cp_async16(uint32_t s, const void* g) {
    asm volatile("cp.async.cg.shared.global [%0], [%1], 16;" :: "r"(s), "l"(g));
}
__device__ __forceinline__ void cp_commit() {
    asm volatile("cp.async.commit_group;");
}
template <int N> __device__ __forceinline__ void cp_wait() {
    asm volatile("cp.async.wait_group %0;" :: "n"(N));
}
__device__ __forceinline__ void ldsm_x4(uint32_t* r, uint32_t a) {
    asm volatile("ldmatrix.sync.aligned.m8n8.x4.shared.b16 {%0,%1,%2,%3}, [%4];"
                 : "=r"(r[0]), "=r"(r[1]), "=r"(r[2]), "=r"(r[3]) : "r"(a));
}
__device__ __forceinline__ void ldsm_x4_t(uint32_t* r, uint32_t a) {
    asm volatile("ldmatrix.sync.aligned.m8n8.x4.trans.shared.b16 {%0,%1,%2,%3}, [%4];"
                 : "=r"(r[0]), "=r"(r[1]), "=r"(r[2]), "=r"(r[3]) : "r"(a));
}
__device__ __forceinline__ void mma_f16(float* d, const uint32_t* a,
                                        uint32_t b0, uint32_t b1) {
    asm volatile(
        "mma.sync.aligned.m16n8k16.row.col.f32.f16.f16.f32 "
        "{%0,%1,%2,%3}, {%4,%5,%6,%7}, {%8,%9}, {%0,%1,%2,%3};"
        : "+f"(d[0]), "+f"(d[1]), "+f"(d[2]), "+f"(d[3])
        : "r"(a[0]), "r"(a[1]), "r"(a[2]), "r"(a[3]), "r"(b0), "r"(b1));
}
__device__ __forceinline__ float elu_fast(float v) {
    return v > 0.0f ? v : (__expf(v) - 1.0f);
}
__device__ __forceinline__ uint32_t h2_bits(__half2 h) {
    __half2_raw r = *reinterpret_cast<__half2_raw*>(&h);
    return (uint32_t)r.x | ((uint32_t)r.y << 16);
}

// ---------------- fused preprocessing --------------------------------------
// One launch converts everything to half:
//   x [M,258] f32 -> xh [M,256]  (4x float2 loads -> one 16B store; x rows are
//   only 8B-aligned: stride 258 floats = 1032B)
//   w1/w2/w3 (contiguous, 16B-aligned) -> half via float4 loads.
__global__ void conv_all_kernel(const float* __restrict__ x, __half* __restrict__ xh,
                                const float* __restrict__ w1, __half* __restrict__ w1h,
                                const float* __restrict__ w2, __half* __restrict__ w2h,
                                const float* __restrict__ w3, __half* __restrict__ w3h,
                                int nx, int n1, int n2, int n3) {
    int idx = blockIdx.x * blockDim.x + threadIdx.x;
    if (idx < nx) {
        // x path: 8 columns per thread
        size_t r = (size_t)idx >> 5;
        int c = (idx & 31) * 8;
        const float* src = x + r * 258 + c;
        float2 v0 = *reinterpret_cast<const float2*>(src);
        float2 v1 = *reinterpret_cast<const float2*>(src + 2);
        float2 v2 = *reinterpret_cast<const float2*>(src + 4);
        float2 v3 = *reinterpret_cast<const float2*>(src + 6);
        uint4 o;
        o.x = h2_bits(__floats2half2_rn(v0.x, v0.y));
        o.y = h2_bits(__floats2half2_rn(v1.x, v1.y));
        o.z = h2_bits(__floats2half2_rn(v2.x, v2.y));
        o.w = h2_bits(__floats2half2_rn(v3.x, v3.y));
        *reinterpret_cast<uint4*>(xh + r * 256 + c) = o;
        return;
    }
    int wi = idx - nx;
    const float* src; __half* dst; int i;
    if (wi < n1)                { src = w1; dst = w1h; i = wi; }
    else if (wi < n1 + n2)      { src = w2; dst = w2h; i = wi - n1; }
    else if (wi < n1 + n2 + n3) { src = w3; dst = w3h; i = wi - n1 - n2; }
    else return;
    float4 v = reinterpret_cast<const float4*>(src)[i];
    reinterpret_cast<__half2*>(dst)[i * 2]     = __floats2half2_rn(v.x, v.y);
    reinterpret_cast<__half2*>(dst)[i * 2 + 1] = __floats2half2_rn(v.z, v.w);
}

// ---------------- main GEMM ------------------------------------------------
// A [Mtot,K] half row-major (lda == K), B [2][K,ldb] half row-major.
// Per CTA: rows blockM..+128, cols blockN..+64 (both modes).
// SMEM tile: 128-byte rows (64 halves); 16B chunk j of row m stored at chunk
// (j ^ (m&7)) -> conflict-free for cp.async writes AND ldmatrix reads.
template <int K, bool DO_ELU, bool OUT_HALF>
__global__ void __launch_bounds__(NTHREADS, 2) hgemm(
    const __half* __restrict__ A,
    const __half* __restrict__ B, size_t modeStride, int ldb,
    const float* __restrict__ bias0, const float* __restrict__ bias1,
    const float* __restrict__ xphase,
    void* __restrict__ Cv, int ldc)
{
    constexpr int A_BYTES = TBM * 128;              // 16384
    constexpr int B_BYTES = TBK * 128;              // 8192 per mode
    constexpr int STAGE   = A_BYTES + 2 * B_BYTES;  // 32768
    constexpr int NK      = K / TBK;

    extern __shared__ char smem[];
    const uint32_t sm = smem_u32(smem);

    const int tid  = threadIdx.x;
    const int wid  = tid >> 5;
    const int lane = tid & 31;
    const int warp_m = wid & 3;      // 4 warps over M (32 rows)
    const int warp_n = wid >> 2;     // 2 warps over N (32 cols)
    const size_t blockM = (size_t)blockIdx.y * TBM;
    const int blockN = blockIdx.x * TBN;

    float acc[2][2][4][4];           // [mode][mtile][ntile][frag]
    #pragma unroll
    for (int m = 0; m < 2; m++)
        #pragma unroll
        for (int i = 0; i < 2; i++)
            #pragma unroll
            for (int j = 0; j < 4; j++)
                #pragma unroll
                for (int q = 0; q < 4; q++) acc[m][i][j][q] = 0.0f;

    auto load_stage = [&](int kt, int buf) {
        const int k0 = kt * TBK;
        const uint32_t st = sm + buf * STAGE;
        // A: 128 rows x 8 chunks = 1024 chunks, 4/thread
        #pragma unroll
        for (int c = 0; c < 4; c++) {
            int p = c * NTHREADS + tid;
            int row = p >> 3, j = p & 7;
            uint32_t dst = st + row * 128 + ((j ^ (row & 7)) << 4);
            cp_async16(dst, A + (blockM + row) * (size_t)K + k0 + j * 8);
        }
        // B: per mode 64 rows x 8 chunks = 512 chunks, 2/thread
        #pragma unroll
        for (int m = 0; m < 2; m++) {
            const __half* Bm = B + m * modeStride;
            const uint32_t bst = st + A_BYTES + m * B_BYTES;
            #pragma unroll
            for (int c = 0; c < 2; c++) {
                int p = c * NTHREADS + tid;
                int row = p >> 3, j = p & 7;
                uint32_t dst = bst + row * 128 + ((j ^ (row & 7)) << 4);
                cp_async16(dst, Bm + (size_t)(k0 + row) * ldb + blockN + j * 8);
            }
        }
        cp_commit();
    };

    auto consume_stage = [&](int i) {
        const uint32_t st = sm + (i % 3) * STAGE;
        #pragma unroll
        for (int kk = 0; kk < 4; kk++) {
            uint32_t a[2][4];
            const int jA = kk * 2 + (lane >> 4);
            #pragma unroll
            for (int mt = 0; mt < 2; mt++) {
                const int m = warp_m * 32 + mt * 16 + (lane & 15);
                ldsm_x4(a[mt], st + m * 128 + ((jA ^ (m & 7)) << 4));
            }
            const int krow = kk * 16 + (lane & 15);
            #pragma unroll
            for (int m = 0; m < 2; m++) {
                const uint32_t bst = st + A_BYTES + m * B_BYTES;
                #pragma unroll
                for (int ntg = 0; ntg < 2; ntg++) {
                    const int jn = warp_n * 4 + ntg * 2 + (lane >> 4);
                    uint32_t b[4];
                    ldsm_x4_t(b, bst + krow * 128 + ((jn ^ (krow & 7)) << 4));
                    mma_f16(acc[m][0][ntg * 2 + 0], a[0], b[0], b[1]);
                    mma_f16(acc[m][0][ntg * 2 + 1], a[0], b[2], b[3]);
                    mma_f16(acc[m][1][ntg * 2 + 0], a[1], b[0], b[1]);
                    mma_f16(acc[m][1][ntg * 2 + 1], a[1], b[2], b[3]);
                }
            }
        }
    };

    // 3-stage circular pipeline, loads 2 ahead, ONE barrier per iteration.
    load_stage(0, 0);
    load_stage(1, 1);

    #pragma unroll
    for (int i = 0; i < NK - 1; i++) {
        cp_wait<1>();
        __syncthreads();                       // all warps done with buf (i-1)%3
        if (i + 2 < NK) load_stage(i + 2, (i + 2) % 3);
        consume_stage(i);
    }
    // peeled final iteration (no further loads, drain all)
    cp_wait<0>();
    __syncthreads();
    consume_stage(NK - 1);

    // ---- epilogue: phase mix + bias + ELU ----------------------------------
    #pragma unroll
    for (int mt = 0; mt < 2; mt++) {
        #pragma unroll
        for (int rr = 0; rr < 2; rr++) {
            const size_t r = blockM + warp_m * 32 + mt * 16 + rr * 8 + (lane >> 2);
            const float2 ph = *reinterpret_cast<const float2*>(xphase + r * 258 + 256);
            const float p0 = ph.x, p1 = ph.y;
            #pragma unroll
            for (int nt = 0; nt < 4; nt++) {
                const int col = blockN + warp_n * 32 + nt * 8 + (lane & 3) * 2;
                float v0 = p0 * acc[0][mt][nt][rr * 2 + 0]
                         + p1 * acc[1][mt][nt][rr * 2 + 0]
                         + p0 * __ldg(bias0 + col) + p1 * __ldg(bias1 + col);
                float v1 = p0 * acc[0][mt][nt][rr * 2 + 1]
                         + p1 * acc[1][mt][nt][rr * 2 + 1]
                         + p0 * __ldg(bias0 + col + 1) + p1 * __ldg(bias1 + col + 1);
                if (DO_ELU) {
                    v0 = elu_fast(v0);
                    v1 = elu_fast(v1);
                }
                if (OUT_HALF) {
                    __half* C = (__half*)Cv;
                    *reinterpret_cast<__half2*>(C + r * ldc + col) =
                        __floats2half2_rn(v0, v1);
                } else {
                    float* C = (float*)Cv;
                    *reinterpret_cast<float2*>(C + r * ldc + col) =
                        make_float2(v0, v1);
                }
            }
        }
    }
}

// ---------------------------------------------------------------------------
extern "C" void kernel_launch(void* const* d_in, const int* in_sizes, int n_in,
                              void* d_out, int out_size)
{
    const float* x  = (const float*)d_in[0];
    const float* w1 = (const float*)d_in[1];
    const float* b1 = (const float*)d_in[2];
    const float* w2 = (const float*)d_in[3];
    const float* b2 = (const float*)d_in[4];
    const float* w3 = (const float*)d_in[5];
    const float* b3 = (const float*)d_in[6];
    float* out = (float*)d_out;

    const int M = 32768, DIN = 256, H = 1024, DOUT = 64;

    __half *xh, *w1h, *w2h, *w3h, *h1, *h2;
    cudaGetSymbolAddress((void**)&xh,  g_xh);
    cudaGetSymbolAddress((void**)&w1h, g_w1h);
    cudaGetSymbolAddress((void**)&w2h, g_w2h);
    cudaGetSymbolAddress((void**)&w3h, g_w3h);
    cudaGetSymbolAddress((void**)&h1,  g_h1);
    cudaGetSymbolAddress((void**)&h2,  g_h2);

    const int SMEM = 3 * (128 * 128 + 2 * 64 * 128);   // 98304 (3 stages)
    cudaFuncSetAttribute((const void*)hgemm<256, true, true>,
                         cudaFuncAttributeMaxDynamicSharedMemorySize, SMEM);
    cudaFuncSetAttribute((const void*)hgemm<1024, true, true>,
                         cudaFuncAttributeMaxDynamicSharedMemorySize, SMEM);
    cudaFuncSetAttribute((const void*)hgemm<1024, false, false>,
                         cudaFuncAttributeMaxDynamicSharedMemorySize, SMEM);

    // fused preprocessing: one launch for x + all weights
    {
        int nx = M * DIN / 8;                          // 1048576 (8 cols/thread)
        int n1 = 2 * DIN * H / 4, n2 = 2 * H * H / 4, n3 = 2 * H * DOUT / 4;
        int total = nx + n1 + n2 + n3;
        conv_all_kernel<<<(total + 255) / 256, 256>>>(
            x, xh, w1, w1h, w2, w2h, w3, w3h, nx, n1, n2, n3);
    }

    dim3 blk(NTHREADS);
    // L1: xh @ w1 -> elu -> h1 (half)
    hgemm<256, true, true><<<dim3(H / TBN, M / TBM), blk, SMEM>>>(
        xh, w1h, (size_t)DIN * H, H, b1, b1 + H, x, h1, H);
    // L2: h1 @ w2 -> elu -> h2 (half)
    hgemm<1024, true, true><<<dim3(H / TBN, M / TBM), blk, SMEM>>>(
        h1, w2h, (size_t)H * H, H, b2, b2 + H, x, h2, H);
    // L3: h2 @ w3 -> out (f32)
    hgemm<1024, false, false><<<dim3(DOUT / TBN, M / TBM), blk, SMEM>>>(
        h2, w3h, (size_t)H * DOUT, DOUT, b3, b3 + DOUT, x, out, DOUT);
}

// round 13
// speedup vs baseline: 1.1807x; 1.0011x over previous
#include <cuda_runtime.h>
#include <cuda_fp16.h>
#include <cstdint>
#include <math.h>

// ---------------------------------------------------------------------------
// PFMLPScaledXY via fp16 mma.sync.m16n8k16 (ptxas target = plain sm_100).
//   Lk(inp) = p0*(inp@Wk0) + p1*(inp@Wk1) + p0*bk0 + p1*bk1
// R13 = R12 (456.7us) + L3 reads h2 in REVERSE M order: the L2-layer writes
// h2 ascending; its last-written rows are still L2-resident (h2=64MB < 126MB
// L2) when L3 starts. Reading newest-first converts most of L3's h2 DRAM
// traffic (measured: ~73MB @ 2.5TB/s, 30.9% DRAM) into L2 hits.
// ---------------------------------------------------------------------------

#define NTHREADS 256
#define TBM 128
#define TBN 64      // per mode
#define TBK 64

// scratch (__device__ globals: allocation-free rule)
__device__ __half g_xh [32768ull * 256];
__device__ __half g_w1h[2ull * 256 * 1024];
__device__ __half g_w2h[2ull * 1024 * 1024];
__device__ __half g_w3h[2ull * 1024 * 64];
__device__ __half g_h1 [32768ull * 1024];
__device__ __half g_h2 [32768ull * 1024];

// ---------------- PTX helpers ----------------------------------------------
__device__ __forceinline__ uint32_t smem_u32(const void* p) {
    return (uint32_t)__cvta_generic_to_shared(p);
}
__device__ __forceinline__ void cp_async16(uint32_t s, const void* g) {
    asm volatile("cp.async.cg.shared.global [%0], [%1], 16;" :: "r"(s), "l"(g));
}
__device__ __forceinline__ void cp_commit() {
    asm volatile("cp.async.commit_group;");
}
template <int N> __device__ __forceinline__ void cp_wait() {
    asm volatile("cp.async.wait_group %0;" :: "n"(N));
}
__device__ __forceinline__ void ldsm_x4(uint32_t* r, uint32_t a) {
    asm volatile("ldmatrix.sync.aligned.m8n8.x4.shared.b16 {%0,%1,%2,%3}, [%4];"
                 : "=r"(r[0]), "=r"(r[1]), "=r"(r[2]), "=r"(r[3]) : "r"(a));
}
__device__ __forceinline__ void ldsm_x4_t(uint32_t* r, uint32_t a) {
    asm volatile("ldmatrix.sync.aligned.m8n8.x4.trans.shared.b16 {%0,%1,%2,%3}, [%4];"
                 : "=r"(r[0]), "=r"(r[1]), "=r"(r[2]), "=r"(r[3]) : "r"(a));
}
__device__ __forceinline__ void mma_f16(float* d, const uint32_t* a,
                                        uint32_t b0, uint32_t b1) {
    asm volatile(
        "mma.sync.aligned.m16n8k16.row.col.f32.f16.f16.f32 "
        "{%0,%1,%2,%3}, {%4,%5,%6,%7}, {%8,%9}, {%0,%1,%2,%3};"
        : "+f"(d[0]), "+f"(d[1]), "+f"(d[2]), "+f"(d[3])
        : "r"(a[0]), "r"(a[1]), "r"(a[2]), "r"(a[3]), "r"(b0), "r"(b1));
}
__device__ __forceinline__ float elu_fast(float v) {
    return v > 0.0f ? v : (__expf(v) - 1.0f);
}
__device__ __forceinline__ uint32_t h2_bits(__half2 h) {
    __half2_raw r = *reinterpret_cast<__half2_raw*>(&h);
    return (uint32_t)r.x | ((uint32_t)r.y << 16);
}

// ---------------- fused preprocessing --------------------------------------
__global__ void conv_all_kernel(const float* __restrict__ x, __half* __restrict__ xh,
                                const float* __restrict__ w1, __half* __restrict__ w1h,
                                const float* __restrict__ w2, __half* __restrict__ w2h,
                                const float* __restrict__ w3, __half* __restrict__ w3h,
                                int nx, int n1, int n2, int n3) {
    int idx = blockIdx.x * blockDim.x + threadIdx.x;
    if (idx < nx) {
        // x path: 8 columns per thread (x rows only 8B-aligned: stride 1032B)
        size_t r = (size_t)idx >> 5;
        int c = (idx & 31) * 8;
        const float* src = x + r * 258 + c;
        float2 v0 = *reinterpret_cast<const float2*>(src);
        float2 v1 = *reinterpret_cast<const float2*>(src + 2);
        float2 v2 = *reinterpret_cast<const float2*>(src + 4);
        float2 v3 = *reinterpret_cast<const float2*>(src + 6);
        uint4 o;
        o.x = h2_bits(__floats2half2_rn(v0.x, v0.y));
        o.y = h2_bits(__floats2half2_rn(v1.x, v1.y));
        o.z = h2_bits(__floats2half2_rn(v2.x, v2.y));
        o.w = h2_bits(__floats2half2_rn(v3.x, v3.y));
        *reinterpret_cast<uint4*>(xh + r * 256 + c) = o;
        return;
    }
    int wi = idx - nx;
    const float* src; __half* dst; int i;
    if (wi < n1)                { src = w1; dst = w1h; i = wi; }
    else if (wi < n1 + n2)      { src = w2; dst = w2h; i = wi - n1; }
    else if (wi < n1 + n2 + n3) { src = w3; dst = w3h; i = wi - n1 - n2; }
    else return;
    float4 v = reinterpret_cast<const float4*>(src)[i];
    reinterpret_cast<__half2*>(dst)[i * 2]     = __floats2half2_rn(v.x, v.y);
    reinterpret_cast<__half2*>(dst)[i * 2 + 1] = __floats2half2_rn(v.z, v.w);
}

// ---------------- main GEMM ------------------------------------------------
// A [Mtot,K] half row-major (lda == K), B [2][K,ldb] half row-major.
// Per CTA: rows blockM..+128, cols blockN..+64 (both modes).
// SMEM tile: 128-byte rows (64 halves); 16B chunk j of row m stored at chunk
// (j ^ (m&7)) -> conflict-free for cp.async writes AND ldmatrix reads.
// REVM: traverse M-tiles in descending order (consume producer's hot L2 end).
template <int K, bool DO_ELU, bool OUT_HALF, bool REVM>
__global__ void __launch_bounds__(NTHREADS, 2) hgemm(
    const __half* __restrict__ A,
    const __half* __restrict__ B, size_t modeStride, int ldb,
    const float* __restrict__ bias0, const float* __restrict__ bias1,
    const float* __restrict__ xphase,
    void* __restrict__ Cv, int ldc)
{
    constexpr int A_BYTES = TBM * 128;              // 16384
    constexpr int B_BYTES = TBK * 128;              // 8192 per mode
    constexpr int STAGE   = A_BYTES + 2 * B_BYTES;  // 32768
    constexpr int NK      = K / TBK;

    extern __shared__ char smem[];
    const uint32_t sm = smem_u32(smem);

    const int tid  = threadIdx.x;
    const int wid  = tid >> 5;
    const int lane = tid & 31;
    const int warp_m = wid & 3;      // 4 warps over M (32 rows)
    const int warp_n = wid >> 2;     // 2 warps over N (32 cols)
    const unsigned by = REVM ? (gridDim.y - 1 - blockIdx.y) : blockIdx.y;
    const size_t blockM = (size_t)by * TBM;
    const int blockN = blockIdx.x * TBN;

    float acc[2][2][4][4];           // [mode][mtile][ntile][frag]
    #pragma unroll
    for (int m = 0; m < 2; m++)
        #pragma unroll
        for (int i = 0; i < 2; i++)
            #pragma unroll
            for (int j = 0; j < 4; j++)
                #pragma unroll
                for (int q = 0; q < 4; q++) acc[m][i][j][q] = 0.0f;

    auto load_stage = [&](int kt, int buf) {
        const int k0 = kt * TBK;
        const uint32_t st = sm + buf * STAGE;
        // A: 128 rows x 8 chunks = 1024 chunks, 4/thread
        #pragma unroll
        for (int c = 0; c < 4; c++) {
            int p = c * NTHREADS + tid;
            int row = p >> 3, j = p & 7;
            uint32_t dst = st + row * 128 + ((j ^ (row & 7)) << 4);
            cp_async16(dst, A + (blockM + row) * (size_t)K + k0 + j * 8);
        }
        // B: per mode 64 rows x 8 chunks = 512 chunks, 2/thread
        #pragma unroll
        for (int m = 0; m < 2; m++) {
            const __half* Bm = B + m * modeStride;
            const uint32_t bst = st + A_BYTES + m * B_BYTES;
            #pragma unroll
            for (int c = 0; c < 2; c++) {
                int p = c * NTHREADS + tid;
                int row = p >> 3, j = p & 7;
                uint32_t dst = bst + row * 128 + ((j ^ (row & 7)) << 4);
                cp_async16(dst, Bm + (size_t)(k0 + row) * ldb + blockN + j * 8);
            }
        }
        cp_commit();
    };

    auto consume_stage = [&](int i) {
        const uint32_t st = sm + (i % 3) * STAGE;
        #pragma unroll
        for (int kk = 0; kk < 4; kk++) {
            uint32_t a[2][4];
            const int jA = kk * 2 + (lane >> 4);
            #pragma unroll
            for (int mt = 0; mt < 2; mt++) {
                const int m = warp_m * 32 + mt * 16 + (lane & 15);
                ldsm_x4(a[mt], st + m * 128 + ((jA ^ (m & 7)) << 4));
            }
            const int krow = kk * 16 + (lane & 15);
            #pragma unroll
            for (int m = 0; m < 2; m++) {
                const uint32_t bst = st + A_BYTES + m * B_BYTES;
                #pragma unroll
                for (int ntg = 0; ntg < 2; ntg++) {
                    const int jn = warp_n * 4 + ntg * 2 + (lane >> 4);
                    uint32_t b[4];
                    ldsm_x4_t(b, bst + krow * 128 + ((jn ^ (krow & 7)) << 4));
                    mma_f16(acc[m][0][ntg * 2 + 0], a[0], b[0], b[1]);
                    mma_f16(acc[m][0][ntg * 2 + 1], a[0], b[2], b[3]);
                    mma_f16(acc[m][1][ntg * 2 + 0], a[1], b[0], b[1]);
                    mma_f16(acc[m][1][ntg * 2 + 1], a[1], b[2], b[3]);
                }
            }
        }
    };

    // 3-stage circular pipeline, loads 2 ahead, ONE barrier per iteration.
    load_stage(0, 0);
    load_stage(1, 1);

    #pragma unroll
    for (int i = 0; i < NK - 1; i++) {
        cp_wait<1>();
        __syncthreads();                       // all warps done with buf (i-1)%3
        if (i + 2 < NK) load_stage(i + 2, (i + 2) % 3);
        consume_stage(i);
    }
    // peeled final iteration (no further loads, drain all)
    cp_wait<0>();
    __syncthreads();
    consume_stage(NK - 1);

    // ---- epilogue: phase mix + bias + ELU ----------------------------------
    #pragma unroll
    for (int mt = 0; mt < 2; mt++) {
        #pragma unroll
        for (int rr = 0; rr < 2; rr++) {
            const size_t r = blockM + warp_m * 32 + mt * 16 + rr * 8 + (lane >> 2);
            const float2 ph = *reinterpret_cast<const float2*>(xphase + r * 258 + 256);
            const float p0 = ph.x, p1 = ph.y;
            #pragma unroll
            for (int nt = 0; nt < 4; nt++) {
                const int col = blockN + warp_n * 32 + nt * 8 + (lane & 3) * 2;
                float v0 = p0 * acc[0][mt][nt][rr * 2 + 0]
                         + p1 * acc[1][mt][nt][rr * 2 + 0]
                         + p0 * __ldg(bias0 + col) + p1 * __ldg(bias1 + col);
                float v1 = p0 * acc[0][mt][nt][rr * 2 + 1]
                         + p1 * acc[1][mt][nt][rr * 2 + 1]
                         + p0 * __ldg(bias0 + col + 1) + p1 * __ldg(bias1 + col + 1);
                if (DO_ELU) {
                    v0 = elu_fast(v0);
                    v1 = elu_fast(v1);
                }
                if (OUT_HALF) {
                    __half* C = (__half*)Cv;
                    *reinterpret_cast<__half2*>(C + r * ldc + col) =
                        __floats2half2_rn(v0, v1);
                } else {
                    float* C = (float*)Cv;
                    *reinterpret_cast<float2*>(C + r * ldc + col) =
                        make_float2(v0, v1);
                }
            }
        }
    }
}

// ---------------------------------------------------------------------------
extern "C" void kernel_launch(void* const* d_in, const int* in_sizes, int n_in,
                              void* d_out, int out_size)
{
    const float* x  = (const float*)d_in[0];
    const float* w1 = (const float*)d_in[1];
    const float* b1 = (const float*)d_in[2];
    const float* w2 = (const float*)d_in[3];
    const float* b2 = (const float*)d_in[4];
    const float* w3 = (const float*)d_in[5];
    const float* b3 = (const float*)d_in[6];
    float* out = (float*)d_out;

    const int M = 32768, DIN = 256, H = 1024, DOUT = 64;

    __half *xh, *w1h, *w2h, *w3h, *h1, *h2;
    cudaGetSymbolAddress((void**)&xh,  g_xh);
    cudaGetSymbolAddress((void**)&w1h, g_w1h);
    cudaGetSymbolAddress((void**)&w2h, g_w2h);
    cudaGetSymbolAddress((void**)&w3h, g_w3h);
    cudaGetSymbolAddress((void**)&h1,  g_h1);
    cudaGetSymbolAddress((void**)&h2,  g_h2);

    const int SMEM = 3 * (128 * 128 + 2 * 64 * 128);   // 98304 (3 stages)
    cudaFuncSetAttribute((const void*)hgemm<256, true, true, false>,
                         cudaFuncAttributeMaxDynamicSharedMemorySize, SMEM);
    cudaFuncSetAttribute((const void*)hgemm<1024, true, true, false>,
                         cudaFuncAttributeMaxDynamicSharedMemorySize, SMEM);
    cudaFuncSetAttribute((const void*)hgemm<1024, false, false, true>,
                         cudaFuncAttributeMaxDynamicSharedMemorySize, SMEM);

    // fused preprocessing: one launch for x + all weights
    {
        int nx = M * DIN / 8;                          // 1048576 (8 cols/thread)
        int n1 = 2 * DIN * H / 4, n2 = 2 * H * H / 4, n3 = 2 * H * DOUT / 4;
        int total = nx + n1 + n2 + n3;
        conv_all_kernel<<<(total + 255) / 256, 256>>>(
            x, xh, w1, w1h, w2, w2h, w3, w3h, nx, n1, n2, n3);
    }

    dim3 blk(NTHREADS);
    // L1: xh @ w1 -> elu -> h1 (half)
    hgemm<256, true, true, false><<<dim3(H / TBN, M / TBM), blk, SMEM>>>(
        xh, w1h, (size_t)DIN * H, H, b1, b1 + H, x, h1, H);
    // L2: h1 @ w2 -> elu -> h2 (half)
    hgemm<1024, true, true, false><<<dim3(H / TBN, M / TBM), blk, SMEM>>>(
        h1, w2h, (size_t)H * H, H, b2, b2 + H, x, h2, H);
    // L3: h2 @ w3 -> out (f32), REVERSE M order (reads h2 newest-first)
    hgemm<1024, false, false, true><<<dim3(DOUT / TBN, M / TBM), blk, SMEM>>>(
        h2, w3h, (size_t)H * DOUT, DOUT, b3, b3 + DOUT, x, out, DOUT);
}